// round 16
// baseline (speedup 1.0000x reference)
#include <cuda_runtime.h>
#include <cuda_fp16.h>
#include <math.h>
#include <stdint.h>

#define NROWS 16384
#define NIN   2048
#define NCLS  100

// Scratch
static __device__ float  g_buf[(size_t)NROWS * NIN];          // z, then warped
static __device__ __half g_apre[(size_t)NROWS * NIN * 2];     // A hi/lo fp16 frags
static __device__ __half g_wpre[(size_t)NIN * NIN * 2];       // W hi/lo fp16 frags
static __device__ __half g_fpre[(size_t)128 * 448 * 8];       // fc hi/lo frags (112xN pad)

// ---------------------------------------------------------------------------
// helpers
// ---------------------------------------------------------------------------
__device__ __forceinline__ uint32_t smem_u32(const void* p) {
    uint32_t a;
    asm("{ .reg .u64 t; cvta.to.shared.u64 t, %1; cvt.u32.u64 %0, t; }" : "=r"(a) : "l"(p));
    return a;
}

__device__ __forceinline__ void h_split(float x, __half& h, __half& l) {
    h = __float2half_rn(x);
    l = __float2half_rn(x - __half2float(h));
}

// split two floats -> packed hi half2 and lo half2 (as u32)
__device__ __forceinline__ void split2(float a, float b, uint32_t& hi, uint32_t& lo) {
    __half ha, la, hb, lb;
    h_split(a, ha, la);
    h_split(b, hb, lb);
    __half2 h2 = __halves2half2(ha, hb);
    __half2 l2 = __halves2half2(la, lb);
    hi = *(uint32_t*)&h2;
    lo = *(uint32_t*)&l2;
}

#define MMA_F16(d, a, b0, b1)                                               \
    asm volatile("mma.sync.aligned.m16n8k16.row.col.f32.f16.f16.f32 "       \
                 "{%0,%1,%2,%3}, {%4,%5,%6,%7}, {%8,%9}, {%0,%1,%2,%3};"    \
                 : "+f"((d)[0]), "+f"((d)[1]), "+f"((d)[2]), "+f"((d)[3])   \
                 : "r"((a).x), "r"((a).y), "r"((a).z), "r"((a).w),          \
                   "r"(b0), "r"(b1))

#define CP_ASYNC16(dst, src) \
    asm volatile("cp.async.cg.shared.global [%0], [%1], 16;" :: "r"(dst), "l"(src) : "memory")
#define CP_COMMIT()  asm volatile("cp.async.commit_group;" ::: "memory")
#define CP_WAIT(n)   asm volatile("cp.async.wait_group %0;" :: "n"(n) : "memory")

// two-float compensated add (FFMA pipe only)
__device__ __forceinline__ float2 df_add(float2 a, float2 b) {
    float s  = a.x + b.x;
    float bb = s - a.x;
    float e  = (a.x - (s - bb)) + (b.x - bb);
    e += a.y + b.y;
    float hi = s + e;
    float lo = e - (hi - s);
    return make_float2(hi, lo);
}

// ---------------------------------------------------------------------------
// Prep A: split x into hi/lo fp16 limbs, fragment-permuted for m16n8k16.
// Chunk (mt, ks16) = 512 uint4 at ((mt*128+ks)*512): hi[mi(8)x32] then lo.
// ---------------------------------------------------------------------------
__global__ void __launch_bounds__(256) prep_a_kernel(const float* __restrict__ A)
{
    const uint32_t u = blockIdx.x * 256 + threadIdx.x;
    const int lane = u & 31;
    const int mi   = (u >> 5) & 7;
    const int ks   = (u >> 8) & 127;
    const int mt   = u >> 15;

    const int r = mt * 128 + mi * 16 + (lane >> 2);
    const int c = ks * 16 + (lane & 3) * 2;
    const float* a0p = A + (size_t)r * NIN + c;
    const float* a1p = a0p + (size_t)8 * NIN;

    uint4 hv, lv;
    split2(a0p[0], a0p[1], hv.x, lv.x);
    split2(a1p[0], a1p[1], hv.y, lv.y);
    split2(a0p[8], a0p[9], hv.z, lv.z);
    split2(a1p[8], a1p[9], hv.w, lv.w);

    uint4* dst = (uint4*)g_apre + ((size_t)mt * 128 + ks) * 512 + mi * 32 + lane;
    dst[0]   = hv;
    dst[256] = lv;
}

// ---------------------------------------------------------------------------
// Prep W: chunk (nt, ks16) = 512 uint4 at ((nt*128+ks)*512): ni(16)x32 of
// {bh0,bh1,bl0,bl1}.
// ---------------------------------------------------------------------------
__global__ void __launch_bounds__(256) prep_w_kernel(const float* __restrict__ W)
{
    const uint32_t u = blockIdx.x * 256 + threadIdx.x;
    const int lane = u & 31;
    const int ni   = (u >> 5) & 15;
    const int ks   = (u >> 9) & 127;
    const int nt   = u >> 16;

    const int n = nt * 128 + ni * 8 + (lane >> 2);
    const int k = ks * 16 + (lane & 3) * 2;
    const float* b = W + (size_t)n * NIN + k;

    uint4 o;
    split2(b[0], b[1], o.x, o.z);
    split2(b[8], b[9], o.y, o.w);

    uint4* dst = (uint4*)g_wpre + ((size_t)nt * 128 + ks) * 512 + ni * 32 + lane;
    *dst = o;
}

// ---------------------------------------------------------------------------
// Prep F: fc_weight [100,2048] -> fragment layout, N padded to 112.
// ---------------------------------------------------------------------------
__global__ void __launch_bounds__(448) prep_f_kernel(const float* __restrict__ F)
{
    const int lane = threadIdx.x & 31;
    const int ni   = threadIdx.x >> 5;      // 0..13
    const int ks   = blockIdx.x;            // 0..127

    const int n = ni * 8 + (lane >> 2);
    const int k = ks * 16 + (lane & 3) * 2;

    float v0 = 0.f, v1 = 0.f, v2 = 0.f, v3 = 0.f;
    if (n < NCLS) {
        const float* p = F + (size_t)n * NIN + k;
        v0 = p[0]; v1 = p[1]; v2 = p[8]; v3 = p[9];
    }
    uint4 o;
    split2(v0, v1, o.x, o.z);
    split2(v2, v3, o.y, o.w);
    ((uint4*)g_fpre)[ks * 448 + ni * 32 + lane] = o;
}

// ---------------------------------------------------------------------------
// GEMM1: fp16 tensor cores, 3-term split. BARRIER-FREE warp-private pipes.
// CTA tile 128x128, 128 threads, warps 2(m)x2(n) -> warp tile 64x64.
// Each warp cp.asyncs EXACTLY the fragments it consumes into a private
// 16 KB/stage smem region, waits only on its OWN groups, and never
// synchronizes with other warps (no __syncthreads in the mainloop).
// Stage = 4 x 16 KB = 64 KB; 3 stages = 192 KB; 1 CTA/SM.
// Warp region per k32 stage (uint4): chunk c in {0,1} at c*512:
//   [0..127]   A hi (mt(4) x 32 lanes)
//   [128..255] A lo
//   [256..511] B   (nt(8) x 32 lanes)
// ---------------------------------------------------------------------------
#define NTS64 64
#define G1_STG_U4 4096                    // uint4 per CTA stage (64 KB)
#define GEMM1_SMEM (3 * 65536)            // 192 KB

__global__ void __launch_bounds__(128, 1)
gemm1_mma_kernel(const float* __restrict__ bias)
{
    extern __shared__ uint4 smq[];
    const uint32_t smb = smem_u32(smq);
    const int tid  = threadIdx.x;
    const int lane = tid & 31;
    const int wid  = tid >> 5;            // 0..3

    const int wm = wid & 1;               // 64 rows
    const int wn = wid >> 1;              // 64 cols

    const uint4* gA = (const uint4*)g_apre + (size_t)blockIdx.y * 128 * 512;
    const uint4* gB = (const uint4*)g_wpre + (size_t)blockIdx.x * 128 * 512;
    // per-warp source bases within each k16 chunk
    const uint4* srcAh = gA + wm * 128;          // hi block, 128 uint4
    const uint4* srcAl = gA + 256 + wm * 128;    // lo block, 128 uint4
    const uint4* srcB  = gB + wn * 256;          // B half, 256 uint4

    // per-warp smem region base (bytes): stage s -> s*65536 + wid*16384
    const uint32_t wbase = smb + wid * 16384;

    float acc[4][8][4] = {};

    // Per-warp stage copy: 32 cp.async per thread? No: 32 per thread total?
    // Per chunk c: Ahi 4/thread + Alo 4/thread + B 8/thread = 16; x2 chunks = 32.
    #define ISSUE(t, s) do {                                                   \
        uint32_t d = wbase + (s) * 65536;                                      \
        _Pragma("unroll")                                                      \
        for (int c = 0; c < 2; ++c) {                                          \
            const int ch = 2 * (t) + c;                                        \
            uint32_t dc = d + c * 512 * 16;                                    \
            _Pragma("unroll")                                                  \
            for (int q = 0; q < 4; ++q) {                                      \
                CP_ASYNC16(dc + (q * 32 + lane) * 16,                          \
                           srcAh + ch * 512 + q * 32 + lane);                  \
                CP_ASYNC16(dc + (128 + q * 32 + lane) * 16,                    \
                           srcAl + ch * 512 + q * 32 + lane);                  \
            }                                                                  \
            _Pragma("unroll")                                                  \
            for (int q = 0; q < 8; ++q)                                        \
                CP_ASYNC16(dc + (256 + q * 32 + lane) * 16,                    \
                           srcB + ch * 512 + q * 32 + lane);                   \
        }                                                                      \
        CP_COMMIT();                                                           \
    } while (0)

    ISSUE(0, 0);
    ISSUE(1, 1);

    for (int t = 0; t < NTS64; ++t) {
        const int s = t % 3;
        if (t == NTS64 - 1) { CP_WAIT(0); } else { CP_WAIT(1); }
        // NO __syncthreads: this warp waits only on its own copies.
        if (t + 2 < NTS64) ISSUE(t + 2, (t + 2) % 3);

        const uint4* wr = (const uint4*)((const char*)smq + wid * 16384 + s * 65536);

        #pragma unroll
        for (int c = 0; c < 2; ++c) {
            uint4 ah[4], al[4];
            #pragma unroll
            for (int mt = 0; mt < 4; ++mt) {
                ah[mt] = wr[c * 512 + mt * 32 + lane];
                al[mt] = wr[c * 512 + 128 + mt * 32 + lane];
            }
            #pragma unroll
            for (int nt = 0; nt < 8; ++nt) {
                const uint4 bv = wr[c * 512 + 256 + nt * 32 + lane];
                // term-major: same-accumulator dependency distance = 4 MMAs
                #pragma unroll
                for (int mt = 0; mt < 4; ++mt)
                    MMA_F16(acc[mt][nt], ah[mt], bv.x, bv.y);
                #pragma unroll
                for (int mt = 0; mt < 4; ++mt)
                    MMA_F16(acc[mt][nt], al[mt], bv.x, bv.y);
                #pragma unroll
                for (int mt = 0; mt < 4; ++mt)
                    MMA_F16(acc[mt][nt], ah[mt], bv.z, bv.w);
            }
        }
    }
    #undef ISSUE

    // epilogue (warp-private accumulators; no sync needed)
    const int bm = blockIdx.y * 128;
    const int bn = blockIdx.x * 128;
    const int r0 = lane >> 2;
    const int c0 = lane & 3;
    #pragma unroll
    for (int mt = 0; mt < 4; ++mt) {
        const int m_lo = bm + wm * 64 + mt * 16 + r0;
        #pragma unroll
        for (int nt = 0; nt < 8; ++nt) {
            const int n = bn + wn * 64 + nt * 8 + c0 * 2;
            const float2 bv = *(const float2*)(bias + n);
            float2 v0, v1;
            v0.x = acc[mt][nt][0] + bv.x;
            v0.y = acc[mt][nt][1] + bv.y;
            v1.x = acc[mt][nt][2] + bv.x;
            v1.y = acc[mt][nt][3] + bv.y;
            *(float2*)(g_buf + (size_t)m_lo * NIN + n)       = v0;
            *(float2*)(g_buf + (size_t)(m_lo + 8) * NIN + n) = v1;
        }
    }
}

// ---------------------------------------------------------------------------
// fast exp (x <= 0): FFMA/ALU only.
// ---------------------------------------------------------------------------
__device__ __forceinline__ float fexp(float x) {
    float t = fmaf(x, 1.4426950408889634f, 12582912.0f);
    int ji = __float_as_int(t) - 0x4B400000;
    float j = t - 12582912.0f;
    float f = fmaf(j, -0.693359375f, x);
    f = fmaf(j, 2.1219444005469057e-4f, f);
    float p = 1.3888889e-3f;
    p = fmaf(p, f, 8.3333333e-3f);
    p = fmaf(p, f, 4.1666668e-2f);
    p = fmaf(p, f, 1.6666667e-1f);
    p = fmaf(p, f, 0.5f);
    p = fmaf(p, f, 1.0f);
    p = fmaf(p, f, 1.0f);
    return p * __int_as_float((ji + 127) << 23);
}

// ---------------------------------------------------------------------------
// Row-wise: softmax -> compensated fp32 cumsum -> interp (no fp64).
// ---------------------------------------------------------------------------
__global__ void __launch_bounds__(256)
warp_rows_kernel(const float* __restrict__ X)
{
    __shared__ float  sx[NIN];
    __shared__ float  spos[NIN];
    __shared__ float  wred[8];
    __shared__ float2 wtot[8];

    const int row  = blockIdx.x;
    const int t    = threadIdx.x;
    const int lane = t & 31;
    const int wid  = t >> 5;
    const float* xr = X + (size_t)row * NIN;
    float* zr = g_buf + (size_t)row * NIN;

    #pragma unroll
    for (int j = 0; j < 2; ++j)
        ((float4*)sx)[t + j * 256] = ((const float4*)xr)[t + j * 256];

    float zv[8];
    *(float4*)(zv)     = *(const float4*)(zr + t * 8);
    *(float4*)(zv + 4) = *(const float4*)(zr + t * 8 + 4);

    float mx = zv[0];
    #pragma unroll
    for (int i = 1; i < 8; ++i) mx = fmaxf(mx, zv[i]);
    #pragma unroll
    for (int d = 16; d; d >>= 1) mx = fmaxf(mx, __shfl_xor_sync(0xffffffffu, mx, d));
    if (lane == 0) wred[wid] = mx;
    __syncthreads();
    float bmax = wred[0];
    #pragma unroll
    for (int i = 1; i < 8; ++i) bmax = fmaxf(bmax, wred[i]);

    float csum[8];
    float run = 0.0f;
    #pragma unroll
    for (int i = 0; i < 8; ++i) {
        run += fexp(zv[i] - bmax);
        csum[i] = run;
    }

    float2 v = make_float2(run, 0.0f);
    #pragma unroll
    for (int d = 1; d < 32; d <<= 1) {
        float uh = __shfl_up_sync(0xffffffffu, v.x, d);
        float ul = __shfl_up_sync(0xffffffffu, v.y, d);
        if (lane >= d) v = df_add(v, make_float2(uh, ul));
    }
    if (lane == 31) wtot[wid] = v;
    __syncthreads();

    float2 tot  = make_float2(0.0f, 0.0f);
    float2 woff = make_float2(0.0f, 0.0f);
    #pragma unroll
    for (int i = 0; i < 8; ++i) {
        if (i == wid) woff = tot;
        tot = df_add(tot, wtot[i]);
    }
    float2 ex   = df_add(v, make_float2(-run, 0.0f));
    float2 base = df_add(woff, ex);

    const float totf = tot.x + tot.y;
    const float invs = (float)(NIN - 1) / totf;

    #pragma unroll
    for (int i = 0; i < 8; ++i) {
        float g = base.x + (base.y + csum[i]);
        float pos = fminf(g * invs, (float)(NIN - 1));
        spos[t * 8 + i] = pos;
    }
    __syncthreads();

    #pragma unroll
    for (int j = 0; j < 8; ++j) {
        const int i = t + j * 256;
        const float pos = spos[i];
        float flf = fminf(floorf(pos), (float)(NIN - 2));
        const int idx = (int)flf;
        const float w  = pos - flf;
        const float y0 = sx[idx], y1 = sx[idx + 1];
        zr[i] = fmaf(w, y1 - y0, y0);
    }
}

// ---------------------------------------------------------------------------
// GEMM2 on fp16 tensor cores: out = warped @ fc^T + fb.
// CTA tile 64 rows x 112 cols, 128 threads, warps 2(m)x2(n) -> warp 32x56.
// Grid 256 (2 CTAs/SM). A split in-kernel; B = g_fpre.
// ---------------------------------------------------------------------------
#define NTSG2 64
#define G2_STG_B 24576
#define GEMM2_SMEM (3 * G2_STG_B)

__global__ void __launch_bounds__(128, 2)
gemm2_mma_kernel(const float* __restrict__ fb, float* __restrict__ out)
{
    extern __shared__ char smc[];
    const uint32_t smb = smem_u32(smc);
    const int tid  = threadIdx.x;
    const int lane = tid & 31;
    const int wid  = tid >> 5;
    const int wm   = wid & 1;             // 32 rows
    const int wn   = wid >> 1;            // 56 cols (7 n-tiles)

    const int bm = blockIdx.x * 64;
    const float* gA = g_buf + (size_t)bm * NIN;
    const uint4* gB = (const uint4*)g_fpre;

    float acc[2][7][4] = {};

    #define ISSUE2(t, s) do {                                                   \
        uint32_t d = smb + (s) * G2_STG_B;                                      \
        _Pragma("unroll")                                                       \
        for (int j = 0; j < 4; ++j) {                                           \
            int idx = tid + j * 128;                                            \
            int r2 = idx >> 3, q = idx & 7;                                     \
            CP_ASYNC16(d + r2 * 160 + q * 16,                                   \
                       gA + (size_t)r2 * NIN + (t) * 32 + q * 4);               \
        }                                                                       \
        _Pragma("unroll")                                                       \
        for (int j = 0; j < 7; ++j) {                                           \
            int idx = tid + j * 128;                                            \
            CP_ASYNC16(d + 10240 + idx * 16, gB + 2 * (t) * 448 + idx);         \
        }                                                                       \
        CP_COMMIT();                                                            \
    } while (0)

    ISSUE2(0, 0);
    ISSUE2(1, 1);

    for (int t = 0; t < NTSG2; ++t) {
        const int s = t % 3;
        if (t == NTSG2 - 1) { CP_WAIT(0); } else { CP_WAIT(1); }
        __syncthreads();
        if (t + 2 < NTSG2) ISSUE2(t + 2, (t + 2) % 3);

        const float* sA = (const float*)(smc + s * G2_STG_B);
        const uint4* sB = (const uint4*)(smc + s * G2_STG_B + 10240);

        #pragma unroll
        for (int c = 0; c < 2; ++c) {
            uint4 ah[2], al[2];
            #pragma unroll
            for (int mt = 0; mt < 2; ++mt) {
                const int r = wm * 32 + mt * 16 + (lane >> 2);
                const float* p = sA + r * 40 + c * 16 + (lane & 3) * 2;
                float2 p0 = *(const float2*)(p);
                float2 p1 = *(const float2*)(p + 8 * 40);
                float2 p2 = *(const float2*)(p + 8);
                float2 p3 = *(const float2*)(p + 8 * 40 + 8);
                split2(p0.x, p0.y, ah[mt].x, al[mt].x);
                split2(p1.x, p1.y, ah[mt].y, al[mt].y);
                split2(p2.x, p2.y, ah[mt].z, al[mt].z);
                split2(p3.x, p3.y, ah[mt].w, al[mt].w);
            }
            #pragma unroll
            for (int nt = 0; nt < 7; ++nt) {
                const uint4 bv = sB[c * 448 + (wn * 7 + nt) * 32 + lane];
                #pragma unroll
                for (int mt = 0; mt < 2; ++mt) {
                    MMA_F16(acc[mt][nt], ah[mt], bv.x, bv.y);
                    MMA_F16(acc[mt][nt], al[mt], bv.x, bv.y);
                    MMA_F16(acc[mt][nt], ah[mt], bv.z, bv.w);
                }
            }
        }
    }
    #undef ISSUE2

    const int r0 = lane >> 2;
    const int c0 = lane & 3;
    #pragma unroll
    for (int mt = 0; mt < 2; ++mt) {
        const int m = bm + wm * 32 + mt * 16 + r0;
        #pragma unroll
        for (int nt = 0; nt < 7; ++nt) {
            const int cidx = (wn * 7 + nt) * 8 + c0 * 2;
            if (cidx < NCLS) {
                const float2 bv = *(const float2*)(fb + cidx);
                float2 v0, v1;
                v0.x = acc[mt][nt][0] + bv.x;
                v0.y = acc[mt][nt][1] + bv.y;
                v1.x = acc[mt][nt][2] + bv.x;
                v1.y = acc[mt][nt][3] + bv.y;
                *(float2*)(out + (size_t)m * NCLS + cidx)       = v0;
                *(float2*)(out + (size_t)(m + 8) * NCLS + cidx) = v1;
            }
        }
    }
}

// ---------------------------------------------------------------------------
extern "C" void kernel_launch(void* const* d_in, const int* in_sizes, int n_in,
                              void* d_out, int out_size)
{
    const float* x  = (const float*)d_in[0];
    const float* w  = (const float*)d_in[1];
    const float* wb = (const float*)d_in[2];
    const float* fw = (const float*)d_in[3];
    const float* fb = (const float*)d_in[4];
    float* out = (float*)d_out;

    cudaFuncSetAttribute(gemm1_mma_kernel,
                         cudaFuncAttributeMaxDynamicSharedMemorySize, GEMM1_SMEM);
    cudaFuncSetAttribute(gemm2_mma_kernel,
                         cudaFuncAttributeMaxDynamicSharedMemorySize, GEMM2_SMEM);

    prep_a_kernel<<<16384, 256>>>(x);
    prep_w_kernel<<<4096, 256>>>(w);
    prep_f_kernel<<<128, 448>>>(fw);

    dim3 g1(NIN / 128, NROWS / 128);          // 16 x 128 = 2048 CTAs, 1/SM
    gemm1_mma_kernel<<<g1, 128, GEMM1_SMEM>>>(wb);
    warp_rows_kernel<<<NROWS, 256>>>(x);
    gemm2_mma_kernel<<<NROWS / 64, 128, GEMM2_SMEM>>>(fb, out);
}

// round 17
// speedup vs baseline: 1.1398x; 1.1398x over previous
#include <cuda_runtime.h>
#include <cuda_fp16.h>
#include <math.h>
#include <stdint.h>

#define NROWS 16384
#define NIN   2048
#define NCLS  100

// Scratch
static __device__ float  g_buf[(size_t)NROWS * NIN];          // z, then warped
static __device__ __half g_apre[(size_t)NROWS * NIN * 2];     // A hi/lo fp16 frags
static __device__ __half g_wpre[(size_t)NIN * NIN * 2];       // W hi/lo fp16 frags
static __device__ __half g_fpre[(size_t)128 * 448 * 8];       // fc hi/lo frags (112xN pad)

// ---------------------------------------------------------------------------
// helpers
// ---------------------------------------------------------------------------
__device__ __forceinline__ uint32_t smem_u32(const void* p) {
    uint32_t a;
    asm("{ .reg .u64 t; cvta.to.shared.u64 t, %1; cvt.u32.u64 %0, t; }" : "=r"(a) : "l"(p));
    return a;
}

__device__ __forceinline__ void h_split(float x, __half& h, __half& l) {
    h = __float2half_rn(x);
    l = __float2half_rn(x - __half2float(h));
}

// split two floats -> packed hi half2 and lo half2 (as u32)
__device__ __forceinline__ void split2(float a, float b, uint32_t& hi, uint32_t& lo) {
    __half ha, la, hb, lb;
    h_split(a, ha, la);
    h_split(b, hb, lb);
    __half2 h2 = __halves2half2(ha, hb);
    __half2 l2 = __halves2half2(la, lb);
    hi = *(uint32_t*)&h2;
    lo = *(uint32_t*)&l2;
}

#define MMA_F16(d, a, b0, b1)                                               \
    asm volatile("mma.sync.aligned.m16n8k16.row.col.f32.f16.f16.f32 "       \
                 "{%0,%1,%2,%3}, {%4,%5,%6,%7}, {%8,%9}, {%0,%1,%2,%3};"    \
                 : "+f"((d)[0]), "+f"((d)[1]), "+f"((d)[2]), "+f"((d)[3])   \
                 : "r"((a).x), "r"((a).y), "r"((a).z), "r"((a).w),          \
                   "r"(b0), "r"(b1))

#define CP_ASYNC16(dst, src) \
    asm volatile("cp.async.cg.shared.global [%0], [%1], 16;" :: "r"(dst), "l"(src) : "memory")
#define CP_COMMIT()  asm volatile("cp.async.commit_group;" ::: "memory")
#define CP_WAIT(n)   asm volatile("cp.async.wait_group %0;" :: "n"(n) : "memory")

// two-float compensated add (FFMA pipe only)
__device__ __forceinline__ float2 df_add(float2 a, float2 b) {
    float s  = a.x + b.x;
    float bb = s - a.x;
    float e  = (a.x - (s - bb)) + (b.x - bb);
    e += a.y + b.y;
    float hi = s + e;
    float lo = e - (hi - s);
    return make_float2(hi, lo);
}

// ---------------------------------------------------------------------------
// Merged prep A + W (one launch; W rides in A's tail).
// A: blocks [0, 16384): split x into hi/lo fp16 limbs, fragment-permuted.
//    Chunk (mt, ks16) = 512 uint4 at ((mt*128+ks)*512): hi[mi(8)x32], lo.
// W: blocks [16384, 20480): chunk (nt, ks16) = 512 uint4: ni(16)x32 of
//    {bh0,bh1,bl0,bl1}.
// ---------------------------------------------------------------------------
__global__ void __launch_bounds__(256)
prep_aw_kernel(const float* __restrict__ A, const float* __restrict__ W)
{
    if (blockIdx.x < 16384) {
        const uint32_t u = blockIdx.x * 256 + threadIdx.x;
        const int lane = u & 31;
        const int mi   = (u >> 5) & 7;
        const int ks   = (u >> 8) & 127;
        const int mt   = u >> 15;

        const int r = mt * 128 + mi * 16 + (lane >> 2);
        const int c = ks * 16 + (lane & 3) * 2;
        const float* a0p = A + (size_t)r * NIN + c;
        const float* a1p = a0p + (size_t)8 * NIN;

        uint4 hv, lv;
        split2(a0p[0], a0p[1], hv.x, lv.x);
        split2(a1p[0], a1p[1], hv.y, lv.y);
        split2(a0p[8], a0p[9], hv.z, lv.z);
        split2(a1p[8], a1p[9], hv.w, lv.w);

        uint4* dst = (uint4*)g_apre + ((size_t)mt * 128 + ks) * 512 + mi * 32 + lane;
        dst[0]   = hv;
        dst[256] = lv;
    } else {
        const uint32_t u = (blockIdx.x - 16384) * 256 + threadIdx.x;
        const int lane = u & 31;
        const int ni   = (u >> 5) & 15;
        const int ks   = (u >> 9) & 127;
        const int nt   = u >> 16;

        const int n = nt * 128 + ni * 8 + (lane >> 2);
        const int k = ks * 16 + (lane & 3) * 2;
        const float* b = W + (size_t)n * NIN + k;

        uint4 o;
        split2(b[0], b[1], o.x, o.z);
        split2(b[8], b[9], o.y, o.w);

        uint4* dst = (uint4*)g_wpre + ((size_t)nt * 128 + ks) * 512 + ni * 32 + lane;
        *dst = o;
    }
}

// ---------------------------------------------------------------------------
// Prep F: fc_weight [100,2048] -> fragment layout, N padded to 112.
// ---------------------------------------------------------------------------
__global__ void __launch_bounds__(448) prep_f_kernel(const float* __restrict__ F)
{
    const int lane = threadIdx.x & 31;
    const int ni   = threadIdx.x >> 5;      // 0..13
    const int ks   = blockIdx.x;            // 0..127

    const int n = ni * 8 + (lane >> 2);
    const int k = ks * 16 + (lane & 3) * 2;

    float v0 = 0.f, v1 = 0.f, v2 = 0.f, v3 = 0.f;
    if (n < NCLS) {
        const float* p = F + (size_t)n * NIN + k;
        v0 = p[0]; v1 = p[1]; v2 = p[8]; v3 = p[9];
    }
    uint4 o;
    split2(v0, v1, o.x, o.z);
    split2(v2, v3, o.y, o.w);
    ((uint4*)g_fpre)[ks * 448 + ni * 32 + lane] = o;
}

// ---------------------------------------------------------------------------
// GEMM1: fp16 tensor cores, 3-term split. CTA tile 128x128, 128 threads,
// warps 2(m)x2(n) -> warp tile 64x64, 2 CTAs/SM, k32 chunks, 3-stage.
// (R12 champion config.) SPLIT-ISSUE: the A-half of stage t+2's copies is
// issued right after the barrier, the B-half + commit after chunk c=0's
// compute — one group per stage (commit defines the group), but the copy
// burst no longer collides with the post-barrier fragment LDS burst.
// ---------------------------------------------------------------------------
#define NTS64 64
#define G1_STG_U4 2048                    // uint4 per stage (32 KB)
#define GEMM1_SMEM (3 * 32768)

__global__ void __launch_bounds__(128, 2)
gemm1_mma_kernel(const float* __restrict__ bias)
{
    extern __shared__ uint4 smq[];
    const uint32_t smb = smem_u32(smq);
    const int tid  = threadIdx.x;
    const int lane = tid & 31;
    const int wid  = tid >> 5;            // 0..3

    const uint4* gA = (const uint4*)g_apre + (size_t)blockIdx.y * 128 * 512;
    const uint4* gB = (const uint4*)g_wpre + (size_t)blockIdx.x * 128 * 512;

    const int wm = wid & 1;               // 64 rows
    const int wn = wid >> 1;              // 64 cols

    float acc[4][8][4] = {};

    #define ISSUE_A(t, s) do {                                                 \
        uint32_t d = smb + (s) * 32768;                                        \
        _Pragma("unroll")                                                      \
        for (int j = 0; j < 8; ++j) {                                          \
            int idx = tid + j * 128;                                           \
            CP_ASYNC16(d + idx * 16, gA + 2 * (t) * 512 + idx);                \
        }                                                                      \
    } while (0)
    #define ISSUE_B(t, s) do {                                                 \
        uint32_t d = smb + (s) * 32768;                                        \
        _Pragma("unroll")                                                      \
        for (int j = 0; j < 8; ++j) {                                          \
            int idx = tid + j * 128;                                           \
            CP_ASYNC16(d + 16384 + idx * 16, gB + 2 * (t) * 512 + idx);        \
        }                                                                      \
        CP_COMMIT();                                                           \
    } while (0)

    ISSUE_A(0, 0); ISSUE_B(0, 0);
    ISSUE_A(1, 1); ISSUE_B(1, 1);

    for (int t = 0; t < NTS64; ++t) {
        const int s = t % 3;
        if (t == NTS64 - 1) { CP_WAIT(0); } else { CP_WAIT(1); }
        __syncthreads();
        const bool more = (t + 2 < NTS64);
        if (more) ISSUE_A(t + 2, (t + 2) % 3);

        const uint4* st = smq + s * G1_STG_U4;

        #pragma unroll
        for (int c = 0; c < 2; ++c) {
            uint4 ah[4], al[4];
            #pragma unroll
            for (int mt = 0; mt < 4; ++mt) {
                const int o = c * 512 + (wm * 4 + mt) * 32 + lane;
                ah[mt] = st[o];
                al[mt] = st[o + 256];
            }
            #pragma unroll
            for (int nt = 0; nt < 8; ++nt) {
                const uint4 bv = st[1024 + c * 512 + (wn * 8 + nt) * 32 + lane];
                // term-major: same-accumulator dependency distance = 4 MMAs
                #pragma unroll
                for (int mt = 0; mt < 4; ++mt)
                    MMA_F16(acc[mt][nt], ah[mt], bv.x, bv.y);
                #pragma unroll
                for (int mt = 0; mt < 4; ++mt)
                    MMA_F16(acc[mt][nt], al[mt], bv.x, bv.y);
                #pragma unroll
                for (int mt = 0; mt < 4; ++mt)
                    MMA_F16(acc[mt][nt], ah[mt], bv.z, bv.w);
            }
            if (c == 0 && more) ISSUE_B(t + 2, (t + 2) % 3);
        }
    }
    #undef ISSUE_A
    #undef ISSUE_B

    // epilogue
    const int bm = blockIdx.y * 128;
    const int bn = blockIdx.x * 128;
    const int r0 = lane >> 2;
    const int c0 = lane & 3;
    #pragma unroll
    for (int mt = 0; mt < 4; ++mt) {
        const int m_lo = bm + wm * 64 + mt * 16 + r0;
        #pragma unroll
        for (int nt = 0; nt < 8; ++nt) {
            const int n = bn + wn * 64 + nt * 8 + c0 * 2;
            const float2 bv = *(const float2*)(bias + n);
            float2 v0, v1;
            v0.x = acc[mt][nt][0] + bv.x;
            v0.y = acc[mt][nt][1] + bv.y;
            v1.x = acc[mt][nt][2] + bv.x;
            v1.y = acc[mt][nt][3] + bv.y;
            *(float2*)(g_buf + (size_t)m_lo * NIN + n)       = v0;
            *(float2*)(g_buf + (size_t)(m_lo + 8) * NIN + n) = v1;
        }
    }
}

// ---------------------------------------------------------------------------
// fast exp (x <= 0): FFMA/ALU only.
// ---------------------------------------------------------------------------
__device__ __forceinline__ float fexp(float x) {
    float t = fmaf(x, 1.4426950408889634f, 12582912.0f);
    int ji = __float_as_int(t) - 0x4B400000;
    float j = t - 12582912.0f;
    float f = fmaf(j, -0.693359375f, x);
    f = fmaf(j, 2.1219444005469057e-4f, f);
    float p = 1.3888889e-3f;
    p = fmaf(p, f, 8.3333333e-3f);
    p = fmaf(p, f, 4.1666668e-2f);
    p = fmaf(p, f, 1.6666667e-1f);
    p = fmaf(p, f, 0.5f);
    p = fmaf(p, f, 1.0f);
    p = fmaf(p, f, 1.0f);
    return p * __int_as_float((ji + 127) << 23);
}

// ---------------------------------------------------------------------------
// Row-wise: softmax -> compensated fp32 cumsum -> interp (no fp64).
// ---------------------------------------------------------------------------
__global__ void __launch_bounds__(256)
warp_rows_kernel(const float* __restrict__ X)
{
    __shared__ float  sx[NIN];
    __shared__ float  spos[NIN];
    __shared__ float  wred[8];
    __shared__ float2 wtot[8];

    const int row  = blockIdx.x;
    const int t    = threadIdx.x;
    const int lane = t & 31;
    const int wid  = t >> 5;
    const float* xr = X + (size_t)row * NIN;
    float* zr = g_buf + (size_t)row * NIN;

    #pragma unroll
    for (int j = 0; j < 2; ++j)
        ((float4*)sx)[t + j * 256] = ((const float4*)xr)[t + j * 256];

    float zv[8];
    *(float4*)(zv)     = *(const float4*)(zr + t * 8);
    *(float4*)(zv + 4) = *(const float4*)(zr + t * 8 + 4);

    float mx = zv[0];
    #pragma unroll
    for (int i = 1; i < 8; ++i) mx = fmaxf(mx, zv[i]);
    #pragma unroll
    for (int d = 16; d; d >>= 1) mx = fmaxf(mx, __shfl_xor_sync(0xffffffffu, mx, d));
    if (lane == 0) wred[wid] = mx;
    __syncthreads();
    float bmax = wred[0];
    #pragma unroll
    for (int i = 1; i < 8; ++i) bmax = fmaxf(bmax, wred[i]);

    float csum[8];
    float run = 0.0f;
    #pragma unroll
    for (int i = 0; i < 8; ++i) {
        run += fexp(zv[i] - bmax);
        csum[i] = run;
    }

    float2 v = make_float2(run, 0.0f);
    #pragma unroll
    for (int d = 1; d < 32; d <<= 1) {
        float uh = __shfl_up_sync(0xffffffffu, v.x, d);
        float ul = __shfl_up_sync(0xffffffffu, v.y, d);
        if (lane >= d) v = df_add(v, make_float2(uh, ul));
    }
    if (lane == 31) wtot[wid] = v;
    __syncthreads();

    float2 tot  = make_float2(0.0f, 0.0f);
    float2 woff = make_float2(0.0f, 0.0f);
    #pragma unroll
    for (int i = 0; i < 8; ++i) {
        if (i == wid) woff = tot;
        tot = df_add(tot, wtot[i]);
    }
    float2 ex   = df_add(v, make_float2(-run, 0.0f));
    float2 base = df_add(woff, ex);

    const float totf = tot.x + tot.y;
    const float invs = (float)(NIN - 1) / totf;

    #pragma unroll
    for (int i = 0; i < 8; ++i) {
        float g = base.x + (base.y + csum[i]);
        float pos = fminf(g * invs, (float)(NIN - 1));
        spos[t * 8 + i] = pos;
    }
    __syncthreads();

    #pragma unroll
    for (int j = 0; j < 8; ++j) {
        const int i = t + j * 256;
        const float pos = spos[i];
        float flf = fminf(floorf(pos), (float)(NIN - 2));
        const int idx = (int)flf;
        const float w  = pos - flf;
        const float y0 = sx[idx], y1 = sx[idx + 1];
        zr[i] = fmaf(w, y1 - y0, y0);
    }
}

// ---------------------------------------------------------------------------
// GEMM2 on fp16 tensor cores: out = warped @ fc^T + fb.
// CTA tile 64 rows x 112 cols, 128 threads, warps 2(m)x2(n) -> warp 32x56.
// Grid 256 (2 CTAs/SM). A split in-kernel; B = g_fpre.
// ---------------------------------------------------------------------------
#define NTSG2 64
#define G2_STG_B 24576
#define GEMM2_SMEM (3 * G2_STG_B)

__global__ void __launch_bounds__(128, 2)
gemm2_mma_kernel(const float* __restrict__ fb, float* __restrict__ out)
{
    extern __shared__ char smc[];
    const uint32_t smb = smem_u32(smc);
    const int tid  = threadIdx.x;
    const int lane = tid & 31;
    const int wid  = tid >> 5;
    const int wm   = wid & 1;             // 32 rows
    const int wn   = wid >> 1;            // 56 cols (7 n-tiles)

    const int bm = blockIdx.x * 64;
    const float* gA = g_buf + (size_t)bm * NIN;
    const uint4* gB = (const uint4*)g_fpre;

    float acc[2][7][4] = {};

    #define ISSUE2(t, s) do {                                                   \
        uint32_t d = smb + (s) * G2_STG_B;                                      \
        _Pragma("unroll")                                                       \
        for (int j = 0; j < 4; ++j) {                                           \
            int idx = tid + j * 128;                                            \
            int r2 = idx >> 3, q = idx & 7;                                     \
            CP_ASYNC16(d + r2 * 160 + q * 16,                                   \
                       gA + (size_t)r2 * NIN + (t) * 32 + q * 4);               \
        }                                                                       \
        _Pragma("unroll")                                                       \
        for (int j = 0; j < 7; ++j) {                                           \
            int idx = tid + j * 128;                                            \
            CP_ASYNC16(d + 10240 + idx * 16, gB + 2 * (t) * 448 + idx);         \
        }                                                                       \
        CP_COMMIT();                                                            \
    } while (0)

    ISSUE2(0, 0);
    ISSUE2(1, 1);

    for (int t = 0; t < NTSG2; ++t) {
        const int s = t % 3;
        if (t == NTSG2 - 1) { CP_WAIT(0); } else { CP_WAIT(1); }
        __syncthreads();
        if (t + 2 < NTSG2) ISSUE2(t + 2, (t + 2) % 3);

        const float* sA = (const float*)(smc + s * G2_STG_B);
        const uint4* sB = (const uint4*)(smc + s * G2_STG_B + 10240);

        #pragma unroll
        for (int c = 0; c < 2; ++c) {
            uint4 ah[2], al[2];
            #pragma unroll
            for (int mt = 0; mt < 2; ++mt) {
                const int r = wm * 32 + mt * 16 + (lane >> 2);
                const float* p = sA + r * 40 + c * 16 + (lane & 3) * 2;
                float2 p0 = *(const float2*)(p);
                float2 p1 = *(const float2*)(p + 8 * 40);
                float2 p2 = *(const float2*)(p + 8);
                float2 p3 = *(const float2*)(p + 8 * 40 + 8);
                split2(p0.x, p0.y, ah[mt].x, al[mt].x);
                split2(p1.x, p1.y, ah[mt].y, al[mt].y);
                split2(p2.x, p2.y, ah[mt].z, al[mt].z);
                split2(p3.x, p3.y, ah[mt].w, al[mt].w);
            }
            #pragma unroll
            for (int nt = 0; nt < 7; ++nt) {
                const uint4 bv = sB[c * 448 + (wn * 7 + nt) * 32 + lane];
                #pragma unroll
                for (int mt = 0; mt < 2; ++mt) {
                    MMA_F16(acc[mt][nt], ah[mt], bv.x, bv.y);
                    MMA_F16(acc[mt][nt], al[mt], bv.x, bv.y);
                    MMA_F16(acc[mt][nt], ah[mt], bv.z, bv.w);
                }
            }
        }
    }
    #undef ISSUE2

    const int r0 = lane >> 2;
    const int c0 = lane & 3;
    #pragma unroll
    for (int mt = 0; mt < 2; ++mt) {
        const int m = bm + wm * 32 + mt * 16 + r0;
        #pragma unroll
        for (int nt = 0; nt < 7; ++nt) {
            const int cidx = (wn * 7 + nt) * 8 + c0 * 2;
            if (cidx < NCLS) {
                const float2 bv = *(const float2*)(fb + cidx);
                float2 v0, v1;
                v0.x = acc[mt][nt][0] + bv.x;
                v0.y = acc[mt][nt][1] + bv.y;
                v1.x = acc[mt][nt][2] + bv.x;
                v1.y = acc[mt][nt][3] + bv.y;
                *(float2*)(out + (size_t)m * NCLS + cidx)       = v0;
                *(float2*)(out + (size_t)(m + 8) * NCLS + cidx) = v1;
            }
        }
    }
}

// ---------------------------------------------------------------------------
extern "C" void kernel_launch(void* const* d_in, const int* in_sizes, int n_in,
                              void* d_out, int out_size)
{
    const float* x  = (const float*)d_in[0];
    const float* w  = (const float*)d_in[1];
    const float* wb = (const float*)d_in[2];
    const float* fw = (const float*)d_in[3];
    const float* fb = (const float*)d_in[4];
    float* out = (float*)d_out;

    cudaFuncSetAttribute(gemm1_mma_kernel,
                         cudaFuncAttributeMaxDynamicSharedMemorySize, GEMM1_SMEM);
    cudaFuncSetAttribute(gemm2_mma_kernel,
                         cudaFuncAttributeMaxDynamicSharedMemorySize, GEMM2_SMEM);

    prep_f_kernel<<<128, 448>>>(fw);
    prep_aw_kernel<<<20480, 256>>>(x, w);

    dim3 g1(NIN / 128, NROWS / 128);          // 16 x 128 = 2048 CTAs, 2/SM
    gemm1_mma_kernel<<<g1, 128, GEMM1_SMEM>>>(wb);
    warp_rows_kernel<<<NROWS, 256>>>(x);
    gemm2_mma_kernel<<<NROWS / 64, 128, GEMM2_SMEM>>>(fb, out);
}